// round 2
// baseline (speedup 1.0000x reference)
#include <cuda_runtime.h>
#include <cuda_bf16.h>
#include <cstdint>

#define TLEN   128
#define HID    768
#define LHU    256
#define G4     1024
#define S_TOT  256
#define NB     8
#define NGRP   (S_TOT / NB)   // 32
#define BATCH  8
#define NSENT  32

typedef unsigned long long u64;

// ---------------- device scratch ----------------
__device__ float g_WihT [2][HID * G4];          // [dir][k][j]
__device__ float g_WhhX [2][LHU * LHU * 4];     // [dir][k][u][gate]
__device__ float g_biasW[2][G4];
__device__ float g_G    [2][(size_t)S_TOT * TLEN * G4];  // pre-gates, 268 MB
__device__ float g_emb  [S_TOT * 2 * LHU];
__device__ float g_WsihT[2][2 * LHU * G4];
__device__ float g_WshhX[2][LHU * LHU * 4];
__device__ float g_biasS[2][G4];
__device__ float g_Gs   [2][S_TOT * G4];
__device__ float g_final[BATCH * 2 * LHU];

// ---------------- helpers ----------------
__device__ __forceinline__ u64 pack2(float lo, float hi) {
    u64 r;
    asm("mov.b64 %0, {%1, %2};" : "=l"(r) : "r"(__float_as_uint(lo)), "r"(__float_as_uint(hi)));
    return r;
}
__device__ __forceinline__ u64 dup2(float x) { return pack2(x, x); }
__device__ __forceinline__ void fma2(u64& a, u64 b, u64 c) {
    asm("fma.rn.f32x2 %0, %1, %2, %0;" : "+l"(a) : "l"(b), "l"(c));
}
__device__ __forceinline__ float2 unpack2(u64 v) {
    unsigned lo, hi;
    asm("mov.b64 {%0, %1}, %2;" : "=r"(lo), "=r"(hi) : "l"(v));
    return make_float2(__uint_as_float(lo), __uint_as_float(hi));
}
__device__ __forceinline__ float sigf(float x) { return 1.f / (1.f + __expf(-x)); }
__device__ __forceinline__ float tanh_(float x) {
    float e = __expf(-2.f * fabsf(x));
    float r = (1.f - e) / (1.f + e);
    return copysignf(r, x);
}

// ---------------- weight prep ----------------
// src[R][C] -> dst[C][R], smem-tiled. block (32,8), grid (C/32, R/32)
__global__ void transpose_k(const float* __restrict__ src, float* __restrict__ dst, int R, int C) {
    __shared__ float tile[32][33];
    int bx = blockIdx.x * 32, by = blockIdx.y * 32;
    int tx = threadIdx.x, ty = threadIdx.y;
#pragma unroll
    for (int i = 0; i < 32; i += 8)
        tile[ty + i][tx] = src[(size_t)(by + ty + i) * C + bx + tx];
    __syncthreads();
#pragma unroll
    for (int i = 0; i < 32; i += 8)
        dst[(size_t)(bx + ty + i) * R + by + tx] = tile[tx][ty + i];
}

// WhhX[((k*256)+u)*4+g] = W[g*256+u][k]  for 4 matrices at once
__global__ void prep_interleave(const float* __restrict__ wlf, const float* __restrict__ wlb,
                                const float* __restrict__ wsf, const float* __restrict__ wsb) {
    int i = blockIdx.x * blockDim.x + threadIdx.x;
    if (i >= LHU * LHU * 4) return;
    int g = i & 3, u = (i >> 2) & 255, k = i >> 10;
    int src = (g * LHU + u) * LHU + k;
    g_WhhX[0][i] = wlf[src]; g_WhhX[1][i] = wlb[src];
    g_WshhX[0][i] = wsf[src]; g_WshhX[1][i] = wsb[src];
}

__global__ void copy_biases(const float* bwf, const float* bwb, const float* bsf, const float* bsb) {
    int i = blockIdx.x * blockDim.x + threadIdx.x;
    if (i < G4) { g_biasW[0][i] = bwf[i]; g_biasW[1][i] = bwb[i];
                  g_biasS[0][i] = bsf[i]; g_biasS[1][i] = bsb[i]; }
}

// ---------------- 128x128x8 fp32 GEMM (f32x2 micro-kernel), C = A*B + bias ----------------
// which==0: A=Ain(Mx768),  B=g_WihT[z],  bias=g_biasW[z],  C=g_G[z]
// which==1: A=g_emb(256x512), B=g_WsihT[z], bias=g_biasS[z], C=g_Gs[z]
__global__ void __launch_bounds__(256) sgemm128(int M, int N, int K, const float* __restrict__ Ain, int which) {
    int z = blockIdx.z;
    const float* A; const float* Bp; const float* bi; float* Cp;
    if (which == 0) { A = Ain;   Bp = g_WihT[z];  bi = g_biasW[z]; Cp = g_G[z];  }
    else            { A = g_emb; Bp = g_WsihT[z]; bi = g_biasS[z]; Cp = g_Gs[z]; }

    __shared__ __align__(16) float As[8 * 128];
    __shared__ __align__(16) float Bs[8 * 128];
    int tid = threadIdx.x;
    A  += (size_t)blockIdx.y * 128 * K;
    Bp += blockIdx.x * 128;
    Cp += (size_t)blockIdx.y * 128 * N + blockIdx.x * 128;

    int irA = tid >> 1, icA = (tid & 1) * 4;
    int irB = tid >> 5, icB = (tid & 31) * 4;
    int tr = (tid >> 4) * 8, tc = (tid & 15) * 8;

    u64 acc[4][8];
#pragma unroll
    for (int i = 0; i < 4; i++)
#pragma unroll
        for (int j = 0; j < 8; j++) acc[i][j] = 0ull;

    for (int kt = 0; kt < K; kt += 8) {
        float4 av = *(const float4*)(A + (size_t)irA * K + icA);
        As[(icA + 0) * 128 + irA] = av.x;
        As[(icA + 1) * 128 + irA] = av.y;
        As[(icA + 2) * 128 + irA] = av.z;
        As[(icA + 3) * 128 + irA] = av.w;
        *(float4*)(Bs + irB * 128 + icB) = *(const float4*)(Bp + (size_t)irB * N + icB);
        __syncthreads();
        A += 8; Bp += (size_t)8 * N;
#pragma unroll
        for (int k = 0; k < 8; k++) {
            ulonglong2 m01 = *(const ulonglong2*)(As + k * 128 + tr);
            ulonglong2 m23 = *(const ulonglong2*)(As + k * 128 + tr + 4);
            float4 n0 = *(const float4*)(Bs + k * 128 + tc);
            float4 n1 = *(const float4*)(Bs + k * 128 + tc + 4);
            u64 mp[4] = { m01.x, m01.y, m23.x, m23.y };
            float nn[8] = { n0.x, n0.y, n0.z, n0.w, n1.x, n1.y, n1.z, n1.w };
#pragma unroll
            for (int j = 0; j < 8; j++) {
                u64 nd = dup2(nn[j]);
#pragma unroll
                for (int i = 0; i < 4; i++) fma2(acc[i][j], mp[i], nd);
            }
        }
        __syncthreads();
    }

    float bb[8];
#pragma unroll
    for (int j = 0; j < 8; j++) bb[j] = bi[blockIdx.x * 128 + tc + j];
#pragma unroll
    for (int i = 0; i < 4; i++) {
        float lo[8], hi[8];
#pragma unroll
        for (int j = 0; j < 8; j++) {
            float2 v = unpack2(acc[i][j]);
            lo[j] = v.x + bb[j]; hi[j] = v.y + bb[j];
        }
        *(float4*)(Cp + (size_t)(tr + 2 * i)     * N + tc)     = make_float4(lo[0], lo[1], lo[2], lo[3]);
        *(float4*)(Cp + (size_t)(tr + 2 * i)     * N + tc + 4) = make_float4(lo[4], lo[5], lo[6], lo[7]);
        *(float4*)(Cp + (size_t)(tr + 2 * i + 1) * N + tc)     = make_float4(hi[0], hi[1], hi[2], hi[3]);
        *(float4*)(Cp + (size_t)(tr + 2 * i + 1) * N + tc + 4) = make_float4(hi[4], hi[5], hi[6], hi[7]);
    }
}

// ---------------- word-level BiLSTM + masked mean pool ----------------
// grid (NGRP, 2), 256 threads. thread = hidden unit u; CTA = NB=8 sequences, one dir.
__global__ void __launch_bounds__(256) word_lstm(const int* __restrict__ mask) {
    int u   = threadIdx.x;
    int grp = blockIdx.x;
    int dir = blockIdx.y;
    int s0  = grp * NB;

    __shared__ __align__(16) float hs[2][LHU][NB];
    __shared__ float ms[NB][TLEN];
    __shared__ float cntS[NB];

    for (int i = u; i < NB * TLEN; i += 256) {
        int n = i >> 7, t = i & 127;
        ms[n][t] = (float)mask[(s0 + n) * TLEN + t];
    }
#pragma unroll
    for (int n = 0; n < NB; n++) hs[0][u][n] = 0.f;
    __syncthreads();
    if (u < NB) {
        float cc = 0.f;
        for (int t = 0; t < TLEN; t++) cc += ms[u][t];
        cntS[u] = cc;
    }

    float c[NB], pool[NB];
#pragma unroll
    for (int n = 0; n < NB; n++) { c[n] = 0.f; pool[n] = 0.f; }

    const float*  Gd = g_G[dir];
    const float4* W4 = (const float4*)g_WhhX[dir];
    int buf = 0;

    for (int step = 0; step < TLEN; step++) {
        int t = dir ? (TLEN - 1 - step) : step;
        u64 acc[4][4];     // [gate][seq-pair]
#pragma unroll
        for (int p = 0; p < 4; p++) {
            const float* g0 = Gd + (size_t)((s0 + 2 * p)     * TLEN + t) * G4 + u;
            const float* g1 = Gd + (size_t)((s0 + 2 * p + 1) * TLEN + t) * G4 + u;
            acc[0][p] = pack2(g0[0],       g1[0]);
            acc[1][p] = pack2(g0[LHU],     g1[LHU]);
            acc[2][p] = pack2(g0[2 * LHU], g1[2 * LHU]);
            acc[3][p] = pack2(g0[3 * LHU], g1[3 * LHU]);
        }

#pragma unroll 4
        for (int k = 0; k < LHU; k++) {
            float4 w = W4[k * LHU + u];
            ulonglong2 h01 = *(const ulonglong2*)&hs[buf][k][0];
            ulonglong2 h23 = *(const ulonglong2*)&hs[buf][k][4];
            u64 hp0 = h01.x, hp1 = h01.y, hp2 = h23.x, hp3 = h23.y;
            u64 d0 = dup2(w.x), d1 = dup2(w.y), d2 = dup2(w.z), d3 = dup2(w.w);
            fma2(acc[0][0], d0, hp0); fma2(acc[0][1], d0, hp1); fma2(acc[0][2], d0, hp2); fma2(acc[0][3], d0, hp3);
            fma2(acc[1][0], d1, hp0); fma2(acc[1][1], d1, hp1); fma2(acc[1][2], d1, hp2); fma2(acc[1][3], d1, hp3);
            fma2(acc[2][0], d2, hp0); fma2(acc[2][1], d2, hp1); fma2(acc[2][2], d2, hp2); fma2(acc[2][3], d2, hp3);
            fma2(acc[3][0], d3, hp0); fma2(acc[3][1], d3, hp1); fma2(acc[3][2], d3, hp2); fma2(acc[3][3], d3, hp3);
        }

        float hn[NB];
#pragma unroll
        for (int p = 0; p < 4; p++) {
            float2 vi = unpack2(acc[0][p]);
            float2 vf = unpack2(acc[1][p]);
            float2 vg = unpack2(acc[2][p]);
            float2 vo = unpack2(acc[3][p]);
            {
                int n = 2 * p;
                float cc = sigf(vf.x) * c[n] + sigf(vi.x) * tanh_(vg.x);
                c[n] = cc; hn[n] = sigf(vo.x) * tanh_(cc);
                pool[n] += ms[n][t] * hn[n];
            }
            {
                int n = 2 * p + 1;
                float cc = sigf(vf.y) * c[n] + sigf(vi.y) * tanh_(vg.y);
                c[n] = cc; hn[n] = sigf(vo.y) * tanh_(cc);
                pool[n] += ms[n][t] * hn[n];
            }
        }
        *(float4*)&hs[buf ^ 1][u][0] = make_float4(hn[0], hn[1], hn[2], hn[3]);
        *(float4*)&hs[buf ^ 1][u][4] = make_float4(hn[4], hn[5], hn[6], hn[7]);
        __syncthreads();
        buf ^= 1;
    }

#pragma unroll
    for (int n = 0; n < NB; n++) {
        float cnt = cntS[n];
        g_emb[(s0 + n) * (2 * LHU) + dir * LHU + u] = (cnt > 0.f) ? (pool[n] / cnt) : 0.f;
    }
}

// ---------------- sentence-level LSTM ----------------
// grid(BATCH), 256 threads. Forward full 32-step scan; backward = single step at t=31.
__global__ void __launch_bounds__(256) sent_lstm() {
    int b = blockIdx.x, u = threadIdx.x;
    __shared__ float h[LHU];
    h[u] = 0.f;
    float c = 0.f;
    __syncthreads();

    const ulonglong2* W2 = (const ulonglong2*)g_WshhX[0];
    for (int t = 0; t < NSENT; t++) {
        const float* gp = g_Gs[0] + (size_t)(b * NSENT + t) * G4;
        u64 aif = pack2(gp[u],           gp[LHU + u]);
        u64 ago = pack2(gp[2 * LHU + u], gp[3 * LHU + u]);
#pragma unroll 8
        for (int k = 0; k < LHU; k++) {
            ulonglong2 w = W2[k * LHU + u];
            u64 hd = dup2(h[k]);
            fma2(aif, w.x, hd);
            fma2(ago, w.y, hd);
        }
        float2 v1 = unpack2(aif), v2 = unpack2(ago);
        float cc = sigf(v1.y) * c + sigf(v1.x) * tanh_(v2.x);
        c = cc;
        float hn = sigf(v2.y) * tanh_(cc);
        __syncthreads();
        h[u] = hn;
        __syncthreads();
    }
    g_final[b * 2 * LHU + u] = h[u];

    // backward at t = NSENT-1: one step from zero carry
    const float* gp = g_Gs[1] + (size_t)(b * NSENT + NSENT - 1) * G4;
    float cc = sigf(gp[u]) * tanh_(gp[2 * LHU + u]);
    g_final[b * 2 * LHU + LHU + u] = sigf(gp[3 * LHU + u]) * tanh_(cc);
}

// ---------------- classifier ----------------
__global__ void classify(const float* __restrict__ cw, const float* __restrict__ cb,
                         float* __restrict__ out) {
    int tid = threadIdx.x;
    if (tid >= 32) return;
    int b = tid >> 2, cc = tid & 3;
    float s = cb[cc];
    for (int k = 0; k < 2 * LHU; k++)
        s += g_final[b * 2 * LHU + k] * cw[cc * 2 * LHU + k];
    out[b * 4 + cc] = s;
}

// ---------------- launch ----------------
extern "C" void kernel_launch(void* const* d_in, const int* in_sizes, int n_in,
                              void* d_out, int out_size) {
    const float* hidden  = (const float*)d_in[0];
    const int*   amask   = (const int*)  d_in[1];
    const float* wl_ih_f = (const float*)d_in[2];
    const float* wl_hh_f = (const float*)d_in[3];
    const float* wl_b_f  = (const float*)d_in[4];
    const float* wl_ih_b = (const float*)d_in[5];
    const float* wl_hh_b = (const float*)d_in[6];
    const float* wl_b_b  = (const float*)d_in[7];
    const float* ws_ih_f = (const float*)d_in[8];
    const float* ws_hh_f = (const float*)d_in[9];
    const float* ws_b_f  = (const float*)d_in[10];
    const float* ws_ih_b = (const float*)d_in[11];
    const float* ws_hh_b = (const float*)d_in[12];
    const float* ws_b_b  = (const float*)d_in[13];
    const float* cls_w   = (const float*)d_in[14];
    const float* cls_b   = (const float*)d_in[15];
    float* out = (float*)d_out;

    float* WihT0  = nullptr; float* WihT1  = nullptr;
    float* WsihT0 = nullptr; float* WsihT1 = nullptr;
    cudaGetSymbolAddress((void**)&WihT0,  g_WihT);
    WihT1  = WihT0 + HID * G4;
    cudaGetSymbolAddress((void**)&WsihT0, g_WsihT);
    WsihT1 = WsihT0 + 2 * LHU * G4;

    dim3 tb(32, 8);
    transpose_k<<<dim3(HID / 32, G4 / 32), tb>>>(wl_ih_f, WihT0, G4, HID);
    transpose_k<<<dim3(HID / 32, G4 / 32), tb>>>(wl_ih_b, WihT1, G4, HID);
    transpose_k<<<dim3((2 * LHU) / 32, G4 / 32), tb>>>(ws_ih_f, WsihT0, G4, 2 * LHU);
    transpose_k<<<dim3((2 * LHU) / 32, G4 / 32), tb>>>(ws_ih_b, WsihT1, G4, 2 * LHU);
    prep_interleave<<<(LHU * LHU * 4 + 255) / 256, 256>>>(wl_hh_f, wl_hh_b, ws_hh_f, ws_hh_b);
    copy_biases<<<4, 256>>>(wl_b_f, wl_b_b, ws_b_f, ws_b_b);

    // word pre-gates: [32768 x 768] @ [768 x 1024] per dir
    sgemm128<<<dim3(G4 / 128, (S_TOT * TLEN) / 128, 2), 256>>>(S_TOT * TLEN, G4, HID, hidden, 0);

    // word BiLSTM + pooling
    word_lstm<<<dim3(NGRP, 2), 256>>>(amask);

    // sentence pre-gates: [256 x 512] @ [512 x 1024] per dir
    sgemm128<<<dim3(G4 / 128, S_TOT / 128, 2), 256>>>(S_TOT, G4, 2 * LHU, nullptr, 1);

    sent_lstm<<<BATCH, 256>>>();
    classify<<<1, 32>>>(cls_w, cls_b, out);
}

// round 4
// speedup vs baseline: 1.4385x; 1.4385x over previous
#include <cuda_runtime.h>
#include <cuda_bf16.h>
#include <cstdint>

#define TLEN   128
#define HID    768
#define LHU    256
#define G4     1024
#define S_TOT  256
#define NB     8
#define NGRP   (S_TOT / NB)   // 32
#define BATCH  8
#define NSENT  32

typedef unsigned long long u64;

// ---------------- device scratch ----------------
__device__ float g_WhhX [2][LHU * LHU * 4];              // [dir][k][u][gate]
__device__ float g_G    [2][(size_t)S_TOT * TLEN * G4];  // word pre-gates (268 MB)
__device__ float g_emb  [S_TOT * 2 * LHU];
__device__ float g_WshhX[2][LHU * LHU * 4];
__device__ float g_Gs   [2][S_TOT * G4];
__device__ float g_final[BATCH * 2 * LHU];

// ---------------- f32x2 helpers (recurrence kernels) ----------------
__device__ __forceinline__ u64 pack2(float lo, float hi) {
    u64 r;
    asm("mov.b64 %0, {%1, %2};" : "=l"(r) : "r"(__float_as_uint(lo)), "r"(__float_as_uint(hi)));
    return r;
}
__device__ __forceinline__ u64 dup2(float x) { return pack2(x, x); }
__device__ __forceinline__ void fma2(u64& a, u64 b, u64 c) {
    asm("fma.rn.f32x2 %0, %1, %2, %0;" : "+l"(a) : "l"(b), "l"(c));
}
__device__ __forceinline__ float2 unpack2(u64 v) {
    unsigned lo, hi;
    asm("mov.b64 {%0, %1}, %2;" : "=r"(lo), "=r"(hi) : "l"(v));
    return make_float2(__uint_as_float(lo), __uint_as_float(hi));
}
__device__ __forceinline__ float sigf(float x) { return 1.f / (1.f + __expf(-x)); }
__device__ __forceinline__ float tanh_(float x) {
    float e = __expf(-2.f * fabsf(x));
    float r = (1.f - e) / (1.f + e);
    return copysignf(r, x);
}
__device__ __forceinline__ uint32_t tf32r(float f) {
    uint32_t o;
    asm("cvt.rna.tf32.f32 %0, %1;" : "=r"(o) : "f"(f));
    return o;
}

// ---------------- tf32 mma.sync GEMM: C[dir] = A @ B[dir]^T + bias[dir] ----------------
// A: [Mtiles*128, K] row-major.  B: [1024, K] row-major (N x K).  C: [Mtiles*128, 1024].
// grid.x = 16 (nt 0..7 | dir<<3), grid.y = Mtiles.  256 threads = 8 warps (4 M x 2 N).
// Warp tile 32x64: 2 m16 tiles x 8 n8 tiles, k-tile 32 (4 k8 steps).
__global__ void __launch_bounds__(256) mma_gemm(
    const float* __restrict__ A,
    const float* __restrict__ B0, const float* __restrict__ B1,
    const float* __restrict__ bias0, const float* __restrict__ bias1,
    float* __restrict__ C0, float* __restrict__ C1,
    int K)
{
    int dir = blockIdx.x >> 3;
    int nt  = blockIdx.x & 7;
    int mt  = blockIdx.y;
    const float* Ap = A + (size_t)mt * 128 * K;
    const float* Bp = (dir ? B1 : B0) + (size_t)nt * 128 * K;
    const float* bi = (dir ? bias1 : bias0) + nt * 128;
    float* Cp = (dir ? C1 : C0) + (size_t)mt * 128 * G4 + nt * 128;

    __shared__ uint32_t As[128][36];
    __shared__ uint32_t Bs[128][36];

    int tid = threadIdx.x;
    int warp = tid >> 5, lane = tid & 31;
    int wm = warp & 3, wn = warp >> 2;          // warp tile origin (wm*32, wn*64)
    int lr = lane >> 2, lc = lane & 3;          // lane row / col within fragment

    float c[2][8][4];
#pragma unroll
    for (int mi = 0; mi < 2; mi++)
#pragma unroll
        for (int ni = 0; ni < 8; ni++)
#pragma unroll
            for (int j = 0; j < 4; j++) c[mi][ni][j] = 0.f;

    int nkt = K >> 5;
    for (int kt = 0; kt < nkt; kt++) {
        __syncthreads();
#pragma unroll
        for (int it = 0; it < 4; it++) {
            int i = tid + it * 256;             // 1024 float4 per tile
            int row = i >> 3, c4 = i & 7;
            float4 va = *(const float4*)(Ap + (size_t)row * K + kt * 32 + c4 * 4);
            float4 vb = *(const float4*)(Bp + (size_t)row * K + kt * 32 + c4 * 4);
            As[row][c4 * 4 + 0] = tf32r(va.x); As[row][c4 * 4 + 1] = tf32r(va.y);
            As[row][c4 * 4 + 2] = tf32r(va.z); As[row][c4 * 4 + 3] = tf32r(va.w);
            Bs[row][c4 * 4 + 0] = tf32r(vb.x); Bs[row][c4 * 4 + 1] = tf32r(vb.y);
            Bs[row][c4 * 4 + 2] = tf32r(vb.z); Bs[row][c4 * 4 + 3] = tf32r(vb.w);
        }
        __syncthreads();

#pragma unroll
        for (int kk = 0; kk < 4; kk++) {
            int k0 = kk * 8;
            uint32_t a[2][4];
#pragma unroll
            for (int mi = 0; mi < 2; mi++) {
                int r = wm * 32 + mi * 16 + lr;
                a[mi][0] = As[r][k0 + lc];
                a[mi][1] = As[r + 8][k0 + lc];
                a[mi][2] = As[r][k0 + lc + 4];
                a[mi][3] = As[r + 8][k0 + lc + 4];
            }
            uint32_t b[8][2];
#pragma unroll
            for (int ni = 0; ni < 8; ni++) {
                int n = wn * 64 + ni * 8 + lr;
                b[ni][0] = Bs[n][k0 + lc];
                b[ni][1] = Bs[n][k0 + lc + 4];
            }
#pragma unroll
            for (int mi = 0; mi < 2; mi++)
#pragma unroll
                for (int ni = 0; ni < 8; ni++) {
                    asm volatile(
                        "mma.sync.aligned.m16n8k8.row.col.f32.tf32.tf32.f32 "
                        "{%0,%1,%2,%3}, {%4,%5,%6,%7}, {%8,%9}, {%0,%1,%2,%3};"
                        : "+f"(c[mi][ni][0]), "+f"(c[mi][ni][1]),
                          "+f"(c[mi][ni][2]), "+f"(c[mi][ni][3])
                        : "r"(a[mi][0]), "r"(a[mi][1]), "r"(a[mi][2]), "r"(a[mi][3]),
                          "r"(b[ni][0]), "r"(b[ni][1]));
                }
        }
    }

    // epilogue: add bias, store float2 pairs
#pragma unroll
    for (int mi = 0; mi < 2; mi++) {
        int r0 = wm * 32 + mi * 16 + lr;
#pragma unroll
        for (int ni = 0; ni < 8; ni++) {
            int col = wn * 64 + ni * 8 + 2 * lc;
            float bx = bi[col], by = bi[col + 1];
            *(float2*)(Cp + (size_t)r0 * G4 + col) =
                make_float2(c[mi][ni][0] + bx, c[mi][ni][1] + by);
            *(float2*)(Cp + (size_t)(r0 + 8) * G4 + col) =
                make_float2(c[mi][ni][2] + bx, c[mi][ni][3] + by);
        }
    }
}

// ---------------- weight prep ----------------
__global__ void prep_interleave(const float* __restrict__ wlf, const float* __restrict__ wlb,
                                const float* __restrict__ wsf, const float* __restrict__ wsb) {
    int i = blockIdx.x * blockDim.x + threadIdx.x;
    if (i >= LHU * LHU * 4) return;
    int g = i & 3, u = (i >> 2) & 255, k = i >> 10;
    int src = (g * LHU + u) * LHU + k;
    g_WhhX[0][i] = wlf[src]; g_WhhX[1][i] = wlb[src];
    g_WshhX[0][i] = wsf[src]; g_WshhX[1][i] = wsb[src];
}

// ---------------- word-level BiLSTM + masked mean pool ----------------
__global__ void __launch_bounds__(256) word_lstm(const int* __restrict__ mask) {
    int u   = threadIdx.x;
    int grp = blockIdx.x;
    int dir = blockIdx.y;
    int s0  = grp * NB;

    __shared__ __align__(16) float hs[2][LHU][NB];
    __shared__ float ms[NB][TLEN];
    __shared__ float cntS[NB];

    for (int i = u; i < NB * TLEN; i += 256) {
        int n = i >> 7, t = i & 127;
        ms[n][t] = (float)mask[(s0 + n) * TLEN + t];
    }
#pragma unroll
    for (int n = 0; n < NB; n++) hs[0][u][n] = 0.f;
    __syncthreads();
    if (u < NB) {
        float cc = 0.f;
        for (int t = 0; t < TLEN; t++) cc += ms[u][t];
        cntS[u] = cc;
    }

    float c[NB], pool[NB];
#pragma unroll
    for (int n = 0; n < NB; n++) { c[n] = 0.f; pool[n] = 0.f; }

    const float*  Gd = g_G[dir];
    const float4* W4 = (const float4*)g_WhhX[dir];
    int buf = 0;

    for (int step = 0; step < TLEN; step++) {
        int t = dir ? (TLEN - 1 - step) : step;
        u64 acc[4][4];
#pragma unroll
        for (int p = 0; p < 4; p++) {
            const float* g0 = Gd + (size_t)((s0 + 2 * p)     * TLEN + t) * G4 + u;
            const float* g1 = Gd + (size_t)((s0 + 2 * p + 1) * TLEN + t) * G4 + u;
            acc[0][p] = pack2(g0[0],       g1[0]);
            acc[1][p] = pack2(g0[LHU],     g1[LHU]);
            acc[2][p] = pack2(g0[2 * LHU], g1[2 * LHU]);
            acc[3][p] = pack2(g0[3 * LHU], g1[3 * LHU]);
        }

#pragma unroll 4
        for (int k = 0; k < LHU; k++) {
            float4 w = W4[k * LHU + u];
            ulonglong2 h01 = *(const ulonglong2*)&hs[buf][k][0];
            ulonglong2 h23 = *(const ulonglong2*)&hs[buf][k][4];
            u64 hp0 = h01.x, hp1 = h01.y, hp2 = h23.x, hp3 = h23.y;
            u64 d0 = dup2(w.x), d1 = dup2(w.y), d2 = dup2(w.z), d3 = dup2(w.w);
            fma2(acc[0][0], d0, hp0); fma2(acc[0][1], d0, hp1); fma2(acc[0][2], d0, hp2); fma2(acc[0][3], d0, hp3);
            fma2(acc[1][0], d1, hp0); fma2(acc[1][1], d1, hp1); fma2(acc[1][2], d1, hp2); fma2(acc[1][3], d1, hp3);
            fma2(acc[2][0], d2, hp0); fma2(acc[2][1], d2, hp1); fma2(acc[2][2], d2, hp2); fma2(acc[2][3], d2, hp3);
            fma2(acc[3][0], d3, hp0); fma2(acc[3][1], d3, hp1); fma2(acc[3][2], d3, hp2); fma2(acc[3][3], d3, hp3);
        }

        float hn[NB];
#pragma unroll
        for (int p = 0; p < 4; p++) {
            float2 vi = unpack2(acc[0][p]);
            float2 vf = unpack2(acc[1][p]);
            float2 vg = unpack2(acc[2][p]);
            float2 vo = unpack2(acc[3][p]);
            {
                int n = 2 * p;
                float cc = sigf(vf.x) * c[n] + sigf(vi.x) * tanh_(vg.x);
                c[n] = cc; hn[n] = sigf(vo.x) * tanh_(cc);
                pool[n] += ms[n][t] * hn[n];
            }
            {
                int n = 2 * p + 1;
                float cc = sigf(vf.y) * c[n] + sigf(vi.y) * tanh_(vg.y);
                c[n] = cc; hn[n] = sigf(vo.y) * tanh_(cc);
                pool[n] += ms[n][t] * hn[n];
            }
        }
        *(float4*)&hs[buf ^ 1][u][0] = make_float4(hn[0], hn[1], hn[2], hn[3]);
        *(float4*)&hs[buf ^ 1][u][4] = make_float4(hn[4], hn[5], hn[6], hn[7]);
        __syncthreads();
        buf ^= 1;
    }

#pragma unroll
    for (int n = 0; n < NB; n++) {
        float cnt = cntS[n];
        g_emb[(s0 + n) * (2 * LHU) + dir * LHU + u] = (cnt > 0.f) ? (pool[n] / cnt) : 0.f;
    }
}

// ---------------- sentence-level LSTM ----------------
__global__ void __launch_bounds__(256) sent_lstm() {
    int b = blockIdx.x, u = threadIdx.x;
    __shared__ float h[LHU];
    h[u] = 0.f;
    float c = 0.f;
    __syncthreads();

    const ulonglong2* W2 = (const ulonglong2*)g_WshhX[0];
    for (int t = 0; t < NSENT; t++) {
        const float* gp = g_Gs[0] + (size_t)(b * NSENT + t) * G4;
        u64 aif = pack2(gp[u],           gp[LHU + u]);
        u64 ago = pack2(gp[2 * LHU + u], gp[3 * LHU + u]);
#pragma unroll 8
        for (int k = 0; k < LHU; k++) {
            ulonglong2 w = W2[k * LHU + u];
            u64 hd = dup2(h[k]);
            fma2(aif, w.x, hd);
            fma2(ago, w.y, hd);
        }
        float2 v1 = unpack2(aif), v2 = unpack2(ago);
        float cc = sigf(v1.y) * c + sigf(v1.x) * tanh_(v2.x);
        c = cc;
        float hn = sigf(v2.y) * tanh_(cc);
        __syncthreads();
        h[u] = hn;
        __syncthreads();
    }
    g_final[b * 2 * LHU + u] = h[u];

    const float* gp = g_Gs[1] + (size_t)(b * NSENT + NSENT - 1) * G4;
    float cc = sigf(gp[u]) * tanh_(gp[2 * LHU + u]);
    g_final[b * 2 * LHU + LHU + u] = sigf(gp[3 * LHU + u]) * tanh_(cc);
}

// ---------------- classifier ----------------
__global__ void classify(const float* __restrict__ cw, const float* __restrict__ cb,
                         float* __restrict__ out) {
    int tid = threadIdx.x;
    if (tid >= 32) return;
    int b = tid >> 2, cc = tid & 3;
    float s = cb[cc];
    for (int k = 0; k < 2 * LHU; k++)
        s += g_final[b * 2 * LHU + k] * cw[cc * 2 * LHU + k];
    out[b * 4 + cc] = s;
}

// ---------------- launch ----------------
extern "C" void kernel_launch(void* const* d_in, const int* in_sizes, int n_in,
                              void* d_out, int out_size) {
    const float* hidden  = (const float*)d_in[0];
    const int*   amask   = (const int*)  d_in[1];
    const float* wl_ih_f = (const float*)d_in[2];
    const float* wl_hh_f = (const float*)d_in[3];
    const float* wl_b_f  = (const float*)d_in[4];
    const float* wl_ih_b = (const float*)d_in[5];
    const float* wl_hh_b = (const float*)d_in[6];
    const float* wl_b_b  = (const float*)d_in[7];
    const float* ws_ih_f = (const float*)d_in[8];
    const float* ws_hh_f = (const float*)d_in[9];
    const float* ws_b_f  = (const float*)d_in[10];
    const float* ws_ih_b = (const float*)d_in[11];
    const float* ws_hh_b = (const float*)d_in[12];
    const float* ws_b_b  = (const float*)d_in[13];
    const float* cls_w   = (const float*)d_in[14];
    const float* cls_b   = (const float*)d_in[15];
    float* out = (float*)d_out;

    float *G0, *Gs0, *emb;
    cudaGetSymbolAddress((void**)&G0,  g_G);
    cudaGetSymbolAddress((void**)&Gs0, g_Gs);
    cudaGetSymbolAddress((void**)&emb, g_emb);
    float* G1  = G0  + (size_t)S_TOT * TLEN * G4;
    float* Gs1 = Gs0 + (size_t)S_TOT * G4;

    prep_interleave<<<(LHU * LHU * 4 + 255) / 256, 256>>>(wl_hh_f, wl_hh_b, ws_hh_f, ws_hh_b);

    // word pre-gates: [32768 x 768] @ [1024 x 768]^T per dir
    mma_gemm<<<dim3(16, (S_TOT * TLEN) / 128), 256>>>(
        hidden, wl_ih_f, wl_ih_b, wl_b_f, wl_b_b, G0, G1, HID);

    word_lstm<<<dim3(NGRP, 2), 256>>>(amask);

    // sentence pre-gates: [256 x 512] @ [1024 x 512]^T per dir
    mma_gemm<<<dim3(16, S_TOT / 128), 256>>>(
        emb, ws_ih_f, ws_ih_b, ws_b_f, ws_b_b, Gs0, Gs1, 2 * LHU);

    sent_lstm<<<BATCH, 256>>>();
    classify<<<1, 32>>>(cls_w, cls_b, out);
}